// round 5
// baseline (speedup 1.0000x reference)
#include <cuda_runtime.h>

#define N    4096
#define NJ   16          // j-chunks per i-block column
#define JC   (N / NJ)    // 256 j per chunk
#define IB   128         // i per block (1 per thread)
#define NBI  (N / IB)    // 32 i-blocks

// Partial feature sums per j-chunk (fixed-order reduction => deterministic)
__device__ float4 g_part[NJ][N][2];
// Completion counters per i-block column (reset by finisher each launch)
__device__ int g_cnt[NBI];

__device__ __forceinline__ float f_ex2(float x) {
    float r; asm("ex2.approx.ftz.f32 %0, %1;" : "=f"(r) : "f"(x)); return r;
}
__device__ __forceinline__ float f_lg2(float x) {
    float r; asm("lg2.approx.ftz.f32 %0, %1;" : "=f"(r) : "f"(x)); return r;
}
__device__ __forceinline__ float f_rcp(float x) {
    float r; asm("rcp.approx.ftz.f32 %0, %1;" : "=f"(r) : "f"(x)); return r;
}
__device__ __forceinline__ float f_sqrt(float x) {
    float r; asm("sqrt.approx.ftz.f32 %0, %1;" : "=f"(r) : "f"(x)); return r;
}

// Per-particle invariants (exactly 8 floats -> two LDS.128 in the hot loop):
//   {t, ra, dec, psi} and {mc30, E, RE, D}
//   exp(-|fa-fb|/100) = min(Ea*REb, Eb*REa), E=exp(f/100), RE=exp(-f/100)
//   dist_ratio = min(Da,Db) * rcp(max(Da,Db))   (FMNMX on ALU pipe + 1 MUFU)
struct Inv { float t, ra, dec, psi, mc30, E, RE, D; };

__device__ __forceinline__ Inv compute_inv(const float* __restrict__ p, int idx) {
    const float* q = p + idx * 15;
    float p0 = q[0], p1 = q[1], p2 = q[2];
    float p3 = q[3], p4 = q[4], p5 = q[5], p7 = q[7];
    float m1 = p0 * 95.0f + 5.0f;
    float m2 = p1 * 95.0f + 5.0f;
    float msum = m1 + m2;
    float mc = f_ex2(0.6f * f_lg2(m1 * m2) - 0.2f * f_lg2(msum));
    const float C = 220.0f * 1.4426950408889634f * 0.01f;   // fisco -> log2 domain /100
    float x = C * f_rcp(msum);
    Inv v;
    v.t = p5; v.ra = p3; v.dec = p4; v.psi = p7;
    v.mc30 = mc * (1.0f / 30.0f);
    v.E  = f_ex2(x);
    v.RE = f_ex2(-x);
    v.D  = p2 * 2950.0f + 50.0f;
    return v;
}

// ---------------------------------------------------------------------------
// Fused kernel: pairwise partial sums; the last block of each i-column also
// runs the reduce + MLP + LayerNorm + GELU + output for its 128 rows.
// grid = (NBI, NJ), IB threads.
// ---------------------------------------------------------------------------
__global__ void __launch_bounds__(IB) fused_kernel(
    const float* __restrict__ p,
    const float* __restrict__ W1, const float* __restrict__ b1,
    const float* __restrict__ ln_g, const float* __restrict__ ln_b,
    const float* __restrict__ W2, const float* __restrict__ b2,
    float* __restrict__ out)
{
    __shared__ float4 sj0[JC];   // t, ra, dec, psi
    __shared__ float4 sj1[JC];   // mc30, E, RE, D
    __shared__ int s_last;

    const int bx = blockIdx.x;
    const int i  = bx * IB + threadIdx.x;
    const int j0 = blockIdx.y * JC;

    for (int k = threadIdx.x; k < JC; k += IB) {
        Inv v = compute_inv(p, j0 + k);
        sj0[k] = make_float4(v.t, v.ra, v.dec, v.psi);
        sj1[k] = make_float4(v.mc30, v.E, v.RE, v.D);
    }
    Inv a = compute_inv(p, i);
    __syncthreads();

    float s_dt = 0.f, s_sky = 0.f, s_ms = 0.f, s_fo = 0.f;
    float s_dr = 0.f, s_dp = 0.f, s_ra = 0.f, s_de = 0.f;

    #pragma unroll 8
    for (int j = 0; j < JC; ++j) {
        const float4 b0 = sj0[j];
        const float4 b1 = sj1[j];
        float dra = a.ra  - b0.y;
        float dde = a.dec - b0.z;
        s_dt += fabsf(a.t   - b0.x);
        s_dp += fabsf(a.psi - b0.w);
        s_ra += fabsf(dra);
        s_de += fabsf(dde);
        s_sky += f_sqrt(fmaf(dra, dra, dde * dde));
        s_ms  += f_rcp(1.0f + fabsf(a.mc30 - b1.x));
        s_fo  += fminf(a.E * b1.z, b1.y * a.RE);
        s_dr  += fminf(a.D, b1.w) * f_rcp(fmaxf(a.D, b1.w));
    }

    g_part[blockIdx.y][i][0] = make_float4(s_dt, s_sky, s_ms, s_fo);
    g_part[blockIdx.y][i][1] = make_float4(s_dr, s_dp, s_ra, s_de);

    // ---- last-block detection for this i-column
    __threadfence();                 // make this thread's partials visible
    __syncthreads();                 // all threads' fences done
    if (threadIdx.x == 0) {
        int old = atomicAdd(&g_cnt[bx], 1);
        s_last = (old == NJ - 1);
        if (old == NJ - 1) g_cnt[bx] = 0;   // reset for next graph replay
    }
    __syncthreads();
    if (!s_last) return;
    __threadfence();                 // acquire: order reads after counter

    // ---- finish: one row per thread (row = i), weights via smem (reuse sj)
    float* sw = reinterpret_cast<float*>(sj0);   // 256 + 512 + 96 + 16 floats
    float* sW1   = sw;          // [256]
    float* sW2   = sw + 256;    // [512]
    float* sb1   = sw + 768;    // [32]
    float* sg    = sw + 800;    // [32]
    float* sbeta = sw + 832;    // [32]
    float* sb2   = sw + 864;    // [16]
    for (int k = threadIdx.x; k < 256; k += IB) sW1[k] = W1[k];
    for (int k = threadIdx.x; k < 512; k += IB) sW2[k] = W2[k];
    if (threadIdx.x < 32) {
        int k = threadIdx.x;
        sb1[k] = b1[k]; sg[k] = ln_g[k]; sbeta[k] = ln_b[k];
        if (k < 16) sb2[k] = b2[k];
    }
    __syncthreads();

    float4 t0 = make_float4(0.f, 0.f, 0.f, 0.f);
    float4 t1 = make_float4(0.f, 0.f, 0.f, 0.f);
    #pragma unroll
    for (int c = 0; c < NJ; ++c) {
        float4 p0 = g_part[c][i][0];
        float4 p1 = g_part[c][i][1];
        t0.x += p0.x; t0.y += p0.y; t0.z += p0.z; t0.w += p0.w;
        t1.x += p1.x; t1.y += p1.y; t1.z += p1.z; t1.w += p1.w;
    }

    // diag = [0,0,1,1,1,0,0,0] cancels the self-pair; /(n-1)
    const float inv = 1.0f / (float)(N - 1);
    float x[8];
    x[0] = t0.x * inv;
    x[1] = t0.y * inv;
    x[2] = (t0.z - 1.0f) * inv;
    x[3] = (t0.w - 1.0f) * inv;
    x[4] = (t1.x - 1.0f) * inv;
    x[5] = t1.y * inv;
    x[6] = t1.z * inv;
    x[7] = t1.w * inv;

    float h[32];
    #pragma unroll
    for (int k = 0; k < 32; ++k) {
        float acc = sb1[k];
        #pragma unroll
        for (int f = 0; f < 8; ++f)
            acc = fmaf(x[f], sW1[f * 32 + k], acc);
        h[k] = acc;
    }

    float mu = 0.f;
    #pragma unroll
    for (int k = 0; k < 32; ++k) mu += h[k];
    mu *= (1.0f / 32.0f);
    float var = 0.f;
    #pragma unroll
    for (int k = 0; k < 32; ++k) {
        float d = h[k] - mu;
        var = fmaf(d, d, var);
    }
    var *= (1.0f / 32.0f);
    float rs = rsqrtf(var + 1e-5f);

    #pragma unroll
    for (int k = 0; k < 32; ++k) {
        float v = fmaf((h[k] - mu) * rs, sg[k], sbeta[k]);
        h[k] = 0.5f * v * (1.0f + erff(v * 0.7071067811865475f));
    }

    float o[16];
    #pragma unroll
    for (int oo = 0; oo < 16; ++oo) {
        float acc = sb2[oo];
        #pragma unroll
        for (int k = 0; k < 32; ++k)
            acc = fmaf(h[k], sW2[k * 16 + oo], acc);
        o[oo] = acc;
    }
    float4* op = reinterpret_cast<float4*>(out + i * 16);
    op[0] = make_float4(o[0],  o[1],  o[2],  o[3]);
    op[1] = make_float4(o[4],  o[5],  o[6],  o[7]);
    op[2] = make_float4(o[8],  o[9],  o[10], o[11]);
    op[3] = make_float4(o[12], o[13], o[14], o[15]);
}

extern "C" void kernel_launch(void* const* d_in, const int* in_sizes, int n_in,
                              void* d_out, int out_size) {
    const float* params = (const float*)d_in[0];
    const float* W1     = (const float*)d_in[1];
    const float* b1     = (const float*)d_in[2];
    const float* ln_g   = (const float*)d_in[3];
    const float* ln_b   = (const float*)d_in[4];
    const float* W2     = (const float*)d_in[5];
    const float* b2     = (const float*)d_in[6];
    float* out = (float*)d_out;

    fused_kernel<<<dim3(NBI, NJ), IB>>>(params, W1, b1, ln_g, ln_b, W2, b2, out);
}

// round 6
// speedup vs baseline: 1.0756x; 1.0756x over previous
#include <cuda_runtime.h>

#define N    4096
#define NJ   32          // j-chunks
#define JC   (N / NJ)    // 128 j per chunk
#define IB   128         // i per block (1 per thread)
#define NBI  (N / IB)    // 32 i-blocks

// Partial feature sums per j-chunk (fixed-order reduction => deterministic)
__device__ float4 g_part[NJ][N][2];

__device__ __forceinline__ float f_ex2(float x) {
    float r; asm("ex2.approx.ftz.f32 %0, %1;" : "=f"(r) : "f"(x)); return r;
}
__device__ __forceinline__ float f_lg2(float x) {
    float r; asm("lg2.approx.ftz.f32 %0, %1;" : "=f"(r) : "f"(x)); return r;
}
__device__ __forceinline__ float f_rcp(float x) {
    float r; asm("rcp.approx.ftz.f32 %0, %1;" : "=f"(r) : "f"(x)); return r;
}
__device__ __forceinline__ float f_sqrt(float x) {
    float r; asm("sqrt.approx.ftz.f32 %0, %1;" : "=f"(r) : "f"(x)); return r;
}

// Per-particle invariants (exactly 8 floats -> two LDS.128 from one base):
//   {t, ra, dec, psi} and {mc30, E, RE, L}
//   exp(-|fa-fb|/100)        = min(Ea*REb, Eb*REa), E=exp2(c*f), RE=exp2(-c*f)
//   min(Da,Db)/max(Da,Db)    = 2^(-|La-Lb|),        L=log2(D)
struct Inv { float t, ra, dec, psi, mc30, E, RE, L; };

__device__ __forceinline__ Inv compute_inv(const float* __restrict__ p, int idx) {
    const float* q = p + idx * 15;
    float p0 = q[0], p1 = q[1], p2 = q[2];
    float p3 = q[3], p4 = q[4], p5 = q[5], p7 = q[7];
    float m1 = p0 * 95.0f + 5.0f;
    float m2 = p1 * 95.0f + 5.0f;
    float msum = m1 + m2;
    float mc = f_ex2(0.6f * f_lg2(m1 * m2) - 0.2f * f_lg2(msum));
    const float C = 220.0f * 1.4426950408889634f * 0.01f;
    float x = C * f_rcp(msum);
    Inv v;
    v.t = p5; v.ra = p3; v.dec = p4; v.psi = p7;
    v.mc30 = mc * (1.0f / 30.0f);
    v.E  = f_ex2(x);
    v.RE = f_ex2(-x);
    v.L  = f_lg2(p2 * 2950.0f + 50.0f);
    return v;
}

// ---------------------------------------------------------------------------
// Pairwise kernel: grid (NBI, NJ) = 1024 blocks of 128 threads.
// ---------------------------------------------------------------------------
__global__ void __launch_bounds__(IB) pairwise_kernel(const float* __restrict__ p) {
    __shared__ float4 sj[JC * 2];   // interleaved {kin, inv} -> one base reg

    const int i  = blockIdx.x * IB + threadIdx.x;
    const int j0 = blockIdx.y * JC;

    for (int k = threadIdx.x; k < JC; k += IB) {
        Inv v = compute_inv(p, j0 + k);
        sj[2 * k + 0] = make_float4(v.t, v.ra, v.dec, v.psi);
        sj[2 * k + 1] = make_float4(v.mc30, v.E, v.RE, v.L);
    }
    Inv a = compute_inv(p, i);
    __syncthreads();

    float s_dt = 0.f, s_sky = 0.f, s_ms = 0.f, s_fo = 0.f;
    float s_dr = 0.f, s_dp = 0.f, s_ra = 0.f, s_de = 0.f;

    #pragma unroll 8
    for (int j = 0; j < JC; ++j) {
        const float4 b0 = sj[2 * j + 0];
        const float4 b1 = sj[2 * j + 1];
        float dra = a.ra  - b0.y;
        float dde = a.dec - b0.z;
        s_dt += fabsf(a.t   - b0.x);
        s_dp += fabsf(a.psi - b0.w);
        s_ra += fabsf(dra);
        s_de += fabsf(dde);
        s_sky += f_sqrt(fmaf(dra, dra, dde * dde));
        s_ms  += f_rcp(1.0f + fabsf(a.mc30 - b1.x));
        s_fo  += fminf(a.E * b1.z, b1.y * a.RE);
        s_dr  += f_ex2(-fabsf(a.L - b1.w));
    }

    g_part[blockIdx.y][i][0] = make_float4(s_dt, s_sky, s_ms, s_fo);
    g_part[blockIdx.y][i][1] = make_float4(s_dr, s_dp, s_ra, s_de);
}

// ---------------------------------------------------------------------------
// Finish: 8 lanes cooperate per row. 128 blocks x 256 threads.
// ---------------------------------------------------------------------------
#define FTB 256
__global__ void __launch_bounds__(FTB) finish_kernel(
    const float* __restrict__ W1, const float* __restrict__ b1,
    const float* __restrict__ ln_g, const float* __restrict__ ln_b,
    const float* __restrict__ W2, const float* __restrict__ b2,
    float* __restrict__ out)
{
    __shared__ float sW1[8 * 32];
    __shared__ float sW2[32 * 16];
    __shared__ float sb1[32], sg[32], sbeta[32], sb2[16];

    for (int k = threadIdx.x; k < 256; k += FTB) sW1[k] = W1[k];
    for (int k = threadIdx.x; k < 512; k += FTB) sW2[k] = W2[k];
    if (threadIdx.x < 32) {
        int k = threadIdx.x;
        sb1[k] = b1[k]; sg[k] = ln_g[k]; sbeta[k] = ln_b[k];
        if (k < 16) sb2[k] = b2[k];
    }
    __syncthreads();

    const int lane = threadIdx.x & 31;
    const int warp = threadIdx.x >> 5;
    const int sub  = lane & 7;          // 0..7 : lane within row-group
    const int rig  = lane >> 3;         // 0..3 : row within warp
    const int i    = blockIdx.x * 32 + warp * 4 + rig;

    // ---- reduce g_part: each lane sums 4 of the 32 chunks, then butterfly
    float t[8] = {0.f,0.f,0.f,0.f,0.f,0.f,0.f,0.f};
    #pragma unroll
    for (int cc = 0; cc < 4; ++cc) {
        int c = sub * 4 + cc;
        float4 p0 = g_part[c][i][0];
        float4 p1 = g_part[c][i][1];
        t[0] += p0.x; t[1] += p0.y; t[2] += p0.z; t[3] += p0.w;
        t[4] += p1.x; t[5] += p1.y; t[6] += p1.z; t[7] += p1.w;
    }
    #pragma unroll
    for (int m = 1; m < 8; m <<= 1) {
        #pragma unroll
        for (int k = 0; k < 8; ++k)
            t[k] += __shfl_xor_sync(0xFFFFFFFFu, t[k], m);
    }

    // diag = [0,0,1,1,1,0,0,0]; /(n-1)
    const float inv = 1.0f / (float)(N - 1);
    float x[8];
    x[0] = t[0] * inv;
    x[1] = t[1] * inv;
    x[2] = (t[2] - 1.0f) * inv;
    x[3] = (t[3] - 1.0f) * inv;
    x[4] = (t[4] - 1.0f) * inv;
    x[5] = t[5] * inv;
    x[6] = t[6] * inv;
    x[7] = t[7] * inv;

    // ---- h = x @ W1 + b1 : this lane owns k = sub*4 .. sub*4+3
    const int k0 = sub * 4;
    float h[4];
    #pragma unroll
    for (int kk = 0; kk < 4; ++kk) {
        float acc = sb1[k0 + kk];
        #pragma unroll
        for (int f = 0; f < 8; ++f)
            acc = fmaf(x[f], sW1[f * 32 + k0 + kk], acc);
        h[kk] = acc;
    }

    // ---- LayerNorm across the 8-lane group (32 values)
    float s1 = h[0] + h[1] + h[2] + h[3];
    #pragma unroll
    for (int m = 1; m < 8; m <<= 1) s1 += __shfl_xor_sync(0xFFFFFFFFu, s1, m);
    float mu = s1 * (1.0f / 32.0f);

    float s2 = 0.f;
    #pragma unroll
    for (int kk = 0; kk < 4; ++kk) {
        float d = h[kk] - mu;
        s2 = fmaf(d, d, s2);
    }
    #pragma unroll
    for (int m = 1; m < 8; m <<= 1) s2 += __shfl_xor_sync(0xFFFFFFFFu, s2, m);
    float rs = rsqrtf(s2 * (1.0f / 32.0f) + 1e-5f);

    // ---- affine + exact GELU (4 erff per lane)
    #pragma unroll
    for (int kk = 0; kk < 4; ++kk) {
        float v = fmaf((h[kk] - mu) * rs, sg[k0 + kk], sbeta[k0 + kk]);
        h[kk] = 0.5f * v * (1.0f + erff(v * 0.7071067811865475f));
    }

    // ---- out = h @ W2 + b2 : partial over this lane's 4 k's, butterfly
    float o[16];
    #pragma unroll
    for (int oo = 0; oo < 16; ++oo) o[oo] = 0.f;
    #pragma unroll
    for (int kk = 0; kk < 4; ++kk) {
        #pragma unroll
        for (int oo = 0; oo < 16; ++oo)
            o[oo] = fmaf(h[kk], sW2[(k0 + kk) * 16 + oo], o[oo]);
    }
    #pragma unroll
    for (int m = 1; m < 8; m <<= 1) {
        #pragma unroll
        for (int oo = 0; oo < 16; ++oo)
            o[oo] += __shfl_xor_sync(0xFFFFFFFFu, o[oo], m);
    }

    if (sub == 0) {
        float4* op = reinterpret_cast<float4*>(out + i * 16);
        op[0] = make_float4(o[0]  + sb2[0],  o[1]  + sb2[1],
                            o[2]  + sb2[2],  o[3]  + sb2[3]);
        op[1] = make_float4(o[4]  + sb2[4],  o[5]  + sb2[5],
                            o[6]  + sb2[6],  o[7]  + sb2[7]);
        op[2] = make_float4(o[8]  + sb2[8],  o[9]  + sb2[9],
                            o[10] + sb2[10], o[11] + sb2[11]);
        op[3] = make_float4(o[12] + sb2[12], o[13] + sb2[13],
                            o[14] + sb2[14], o[15] + sb2[15]);
    }
}

extern "C" void kernel_launch(void* const* d_in, const int* in_sizes, int n_in,
                              void* d_out, int out_size) {
    const float* params = (const float*)d_in[0];
    const float* W1     = (const float*)d_in[1];
    const float* b1     = (const float*)d_in[2];
    const float* ln_g   = (const float*)d_in[3];
    const float* ln_b   = (const float*)d_in[4];
    const float* W2     = (const float*)d_in[5];
    const float* b2     = (const float*)d_in[6];
    float* out = (float*)d_out;

    pairwise_kernel<<<dim3(NBI, NJ), IB>>>(params);
    finish_kernel<<<N * 8 / FTB, FTB>>>(W1, b1, ln_g, ln_b, W2, b2, out);
}